// round 14
// baseline (speedup 1.0000x reference)
#include <cuda_runtime.h>
#include <cuda_fp16.h>
#include <cstdint>

namespace {
constexpr int NE = 8, NM = 2048, NH = 2048, NF = 7168;

constexpr int BM = 128, BK = 64;           // A rows: 64 fp16 = 128B
constexpr int STAGES = 3;
constexpr int NT = 256;                    // 8 warps

// gemm2 (single-B): BN=128, warp tile 32x64; B tile [BK k-rows][128 n] = 256B/row
constexpr int BN2 = 128;
constexpr int TILE_A  = BM * BK * 2;           // 16384 B
constexpr int TILE_B2 = BK * BN2 * 2;          // 16384 B
constexpr int STG2_B  = TILE_A + TILE_B2;      // 32 KB
constexpr unsigned SMEM2 = STAGES * STG2_B;    // 96 KB

// fused dual gemm1 (B1+B3): BN=64; B tile [BK k-rows][64 n] = 128B/row
constexpr int BN1 = 64;
constexpr int TILE_B1 = BK * BN1 * 2;          // 8192 B
constexpr int STG1_B  = TILE_A + 2 * TILE_B1;  // 32 KB
constexpr unsigned SMEM1 = STAGES * STG1_B;    // 96 KB
}

// ---------------------------------------------------------------------------
// Static device scratch (no cudaMalloc allowed) — all plain fp16 copies,
// SAME layout as the fp32 originals (no transpose needed anymore).
// ---------------------------------------------------------------------------
__device__ __half g_xc [(size_t)NE * NM * NH];   // x   [M, K=H]
__device__ __half g_w1c[(size_t)NE * NH * NF];   // w1  [K=H, N=F]
__device__ __half g_w3c[(size_t)NE * NH * NF];   // w3  [K=H, N=F]
__device__ __half g_w2c[(size_t)NE * NF * NH];   // w2  [K=F, N=H]
__device__ __half g_hid[(size_t)NE * NM * NF];   // hidden [M, K=F]

// ---------------------------------------------------------------------------
// helpers
// ---------------------------------------------------------------------------
__device__ __forceinline__ void cp16(uint32_t dst, const void* src) {
    asm volatile("cp.async.cg.shared.global [%0], [%1], 16;\n" :: "r"(dst), "l"(src));
}
__device__ __forceinline__ void cp_commit() {
    asm volatile("cp.async.commit_group;\n");
}
template <int N> __device__ __forceinline__ void cp_wait() {
    asm volatile("cp.async.wait_group %0;\n" :: "n"(N));
}
__device__ __forceinline__ void ldm4(uint32_t& r0, uint32_t& r1,
                                     uint32_t& r2, uint32_t& r3, uint32_t addr) {
    asm volatile("ldmatrix.sync.aligned.m8n8.x4.shared.b16 {%0,%1,%2,%3}, [%4];"
                 : "=r"(r0), "=r"(r1), "=r"(r2), "=r"(r3) : "r"(addr));
}
__device__ __forceinline__ void ldm4t(uint32_t& r0, uint32_t& r1,
                                      uint32_t& r2, uint32_t& r3, uint32_t addr) {
    asm volatile("ldmatrix.sync.aligned.m8n8.x4.trans.shared.b16 {%0,%1,%2,%3}, [%4];"
                 : "=r"(r0), "=r"(r1), "=r"(r2), "=r"(r3) : "r"(addr));
}
__device__ __forceinline__ void mma_f16(float* c, const uint32_t* a,
                                        uint32_t b0, uint32_t b1) {
    asm volatile(
        "mma.sync.aligned.m16n8k16.row.col.f32.f16.f16.f32 "
        "{%0,%1,%2,%3}, {%4,%5,%6,%7}, {%8,%9}, {%0,%1,%2,%3};"
        : "+f"(c[0]), "+f"(c[1]), "+f"(c[2]), "+f"(c[3])
        : "r"(a[0]), "r"(a[1]), "r"(a[2]), "r"(a[3]), "r"(b0), "r"(b1));
}

// ---------------------------------------------------------------------------
// Elementwise fp32 -> fp16 (fully coalesced, no smem)
// ---------------------------------------------------------------------------
__global__ void conv_h(const float4* __restrict__ in, __half2* __restrict__ out,
                       int n4) {
    int i = blockIdx.x * blockDim.x + threadIdx.x;
    if (i >= n4) return;
    float4 v = in[i];
    out[2 * i + 0] = __floats2half2_rn(v.x, v.y);
    out[2 * i + 1] = __floats2half2_rn(v.z, v.w);
}

// ---------------------------------------------------------------------------
// Fused dual GEMM1 + SwiGLU: hid = fp16( silu(x*w1) * (x*w3) )
//   A [M,K] row-major; B1,B3 [K,N] row-major (weights as-is).
//   grid (NM/BM, NF/BN1, NE); 8 warps 4(m)x2(n); warp tile 32x32 per output.
// A smem: row m (128B), chunk c(0..7)=k8: off = m*128 + ((c^(m&7))<<4)
// B smem: row k (128B, 64 n),  chunk c(0..7)=n8: off = k*128 + ((c^(k&7))<<4)
// ---------------------------------------------------------------------------
__global__ void __launch_bounds__(NT, 2)
gemm1_swiglu(const __half* __restrict__ Ag, const __half* __restrict__ B1g,
             const __half* __restrict__ B3g, __half* __restrict__ Hg) {
    extern __shared__ char smc[];
    const int e  = blockIdx.z;
    const int m0 = blockIdx.x * BM;
    const int n0 = blockIdx.y * BN1;

    const __half* A  = Ag  + (size_t)e * NM * NH;
    const __half* B1 = B1g + (size_t)e * (size_t)NH * NF;
    const __half* B3 = B3g + (size_t)e * (size_t)NH * NF;
    __half*       H  = Hg  + (size_t)e * (size_t)NM * NF;

    const int tid  = threadIdx.x;
    const int warp = tid >> 5;
    const int l    = tid & 31;
    const int wm   = warp >> 1;      // m rows wm*32
    const int wn   = warp & 1;       // n cols wn*32
    const int lr7  = l & 7;

    const uint32_t smem0 = (uint32_t)__cvta_generic_to_shared(smc);

    // A ldmatrix (row-major, non-trans): lanes 0-7 rows lo-16B etc.
    const int a_row = wm * 32 + ((l >> 3) & 1) * 8 + lr7;  // + mt*16
    const int a_cb  = (l >> 4) & 1;                        // k8 sub-chunk
    // B ldmatrix.trans (K-major): lanes 0-7 k0-7/n0, 8-15 k8-15/n0,
    //                             16-23 k0-7/n8, 24-31 k8-15/n8
    const int bk_l  = ((l >> 3) & 1) * 8 + lr7;            // k-lane within k16
    const int bn_h  = (l >> 4) & 1;                        // n8 sub-chunk

    // fills
    const int f_row = tid >> 3;      // +32 rows/step
    const int f_c   = tid & 7;

    float ac1[2][4][4], ac3[2][4][4];
#pragma unroll
    for (int i = 0; i < 2; i++)
#pragma unroll
        for (int j = 0; j < 4; j++)
#pragma unroll
            for (int t = 0; t < 4; t++) { ac1[i][j][t] = 0.f; ac3[i][j][t] = 0.f; }

    auto fill = [&](int st, int kt) {
        uint32_t sa  = smem0 + st * STG1_B;
        uint32_t sb1 = sa + TILE_A;
        uint32_t sb3 = sb1 + TILE_B1;
#pragma unroll
        for (int i = 0; i < 4; i++) {     // A: 128 rows x 8 chunks
            int row = f_row + i * 32;
            uint32_t off = row * 128 + ((f_c ^ (row & 7)) << 4);
            cp16(sa + off, A + (size_t)(m0 + row) * NH + kt + f_c * 8);
        }
#pragma unroll
        for (int i = 0; i < 2; i++) {     // B: 64 k-rows x 8 chunks, two tiles
            int row = f_row + i * 32;
            if (row < BK) {
                uint32_t off = row * 128 + ((f_c ^ (row & 7)) << 4);
                size_t g = (size_t)(kt + row) * NF + n0 + f_c * 8;
                cp16(sb1 + off, B1 + g);
                cp16(sb3 + off, B3 + g);
            }
        }
    };

    const int NIT = NH / BK;   // 32
    fill(0, 0);  cp_commit();
    fill(1, BK); cp_commit();

    for (int it = 0; it < NIT; it++) {
        cp_wait<1>();
        __syncthreads();

        int nt = it + 2;
        if (nt < NIT) fill(nt % STAGES, nt * BK);
        cp_commit();

        uint32_t sa  = smem0 + (it % STAGES) * STG1_B;
        uint32_t sb1 = sa + TILE_A;
        uint32_t sb3 = sb1 + TILE_B1;

#pragma unroll
        for (int kk = 0; kk < 4; kk++) {        // k16 steps
            uint32_t a[2][4], b1[2][4], b3[2][4];
#pragma unroll
            for (int mt = 0; mt < 2; mt++) {
                int row = a_row + mt * 16;
                int ch  = 2 * kk + a_cb;
                ldm4(a[mt][0], a[mt][1], a[mt][2], a[mt][3],
                     sa + row * 128 + ((ch ^ lr7) << 4));
            }
#pragma unroll
            for (int ntl = 0; ntl < 2; ntl++) {   // n16 tiles within warp's 32 n
                int kr = kk * 16 + bk_l;
                int cn = wn * 4 + ntl * 2 + bn_h;
                uint32_t so = kr * 128 + ((cn ^ (kr & 7)) << 4);
                ldm4t(b1[ntl][0], b1[ntl][1], b1[ntl][2], b1[ntl][3], sb1 + so);
                ldm4t(b3[ntl][0], b3[ntl][1], b3[ntl][2], b3[ntl][3], sb3 + so);
            }
#pragma unroll
            for (int mt = 0; mt < 2; mt++)
#pragma unroll
                for (int ntl = 0; ntl < 2; ntl++) {
                    mma_f16(ac1[mt][2 * ntl + 0], a[mt], b1[ntl][0], b1[ntl][1]);
                    mma_f16(ac1[mt][2 * ntl + 1], a[mt], b1[ntl][2], b1[ntl][3]);
                    mma_f16(ac3[mt][2 * ntl + 0], a[mt], b3[ntl][0], b3[ntl][1]);
                    mma_f16(ac3[mt][2 * ntl + 1], a[mt], b3[ntl][2], b3[ntl][3]);
                }
        }
    }

    // SwiGLU epilogue (identical fragment mappings), store fp16 hidden.
    const int erow = m0 + wm * 32 + (l >> 2);
    const int ecol = n0 + wn * 32 + 2 * (l & 3);
#pragma unroll
    for (int mt = 0; mt < 2; mt++)
#pragma unroll
        for (int j = 0; j < 4; j++) {
            float v0 = ac1[mt][j][0], v1 = ac1[mt][j][1];
            float v2 = ac1[mt][j][2], v3 = ac1[mt][j][3];
            float h0 = v0 / (1.0f + __expf(-v0)) * ac3[mt][j][0];
            float h1 = v1 / (1.0f + __expf(-v1)) * ac3[mt][j][1];
            float h2 = v2 / (1.0f + __expf(-v2)) * ac3[mt][j][2];
            float h3 = v3 / (1.0f + __expf(-v3)) * ac3[mt][j][3];
            __half* p0 = H + (size_t)(erow + mt * 16) * NF + ecol + j * 8;
            *reinterpret_cast<__half2*>(p0)          = __floats2half2_rn(h0, h1);
            *reinterpret_cast<__half2*>(p0 + 8 * NF) = __floats2half2_rn(h2, h3);
        }
}

// ---------------------------------------------------------------------------
// GEMM2: out = hid * w2   A [M,K=F] fp16, B=w2 [K=F,N=H] fp16, C fp32.
//   grid (NM/BM, NH/BN2, NE); warp tile 32x64.
// B smem: row k (256B, 128 n), chunk c(0..15)=n8:
//   off = k*256 + ((c ^ ((k&7)<<1)) << 4)
// ---------------------------------------------------------------------------
__global__ void __launch_bounds__(NT, 2)
gemm_f16(const __half* __restrict__ Ag, const __half* __restrict__ Bg,
         float* __restrict__ Cg, int N, int K) {
    extern __shared__ char smc[];
    const int e  = blockIdx.z;
    const int m0 = blockIdx.x * BM;
    const int n0 = blockIdx.y * BN2;

    const __half* A = Ag + (size_t)e * NM * K;
    const __half* B = Bg + (size_t)e * (size_t)K * N;
    float*        C = Cg + (size_t)e * NM * N;

    const int tid  = threadIdx.x;
    const int warp = tid >> 5;
    const int l    = tid & 31;
    const int wm   = warp >> 1;
    const int wn   = warp & 1;       // cols wn*64
    const int lr7  = l & 7;

    const uint32_t smem0 = (uint32_t)__cvta_generic_to_shared(smc);

    const int a_row = wm * 32 + ((l >> 3) & 1) * 8 + lr7;
    const int a_cb  = (l >> 4) & 1;
    const int bk_l  = ((l >> 3) & 1) * 8 + lr7;
    const int bn_h  = (l >> 4) & 1;

    const int fa_row = tid >> 3,  fa_c = tid & 7;     // A fill
    const int fb_row = tid >> 4,  fb_c = tid & 15;    // B fill (16 chunks/row)

    float acc[2][8][4];
#pragma unroll
    for (int i = 0; i < 2; i++)
#pragma unroll
        for (int j = 0; j < 8; j++)
#pragma unroll
            for (int t = 0; t < 4; t++) acc[i][j][t] = 0.0f;

    auto fill = [&](int st, int kt) {
        uint32_t sa = smem0 + st * STG2_B;
        uint32_t sb = sa + TILE_A;
#pragma unroll
        for (int i = 0; i < 4; i++) {     // A: 128 rows x 8 chunks
            int row = fa_row + i * 32;
            uint32_t off = row * 128 + ((fa_c ^ (row & 7)) << 4);
            cp16(sa + off, A + (size_t)(m0 + row) * K + kt + fa_c * 8);
        }
#pragma unroll
        for (int i = 0; i < 4; i++) {     // B: 64 k-rows x 16 chunks
            int row = fb_row + i * 16;
            uint32_t off = row * 256 + ((fb_c ^ ((row & 7) << 1)) << 4);
            cp16(sb + off, B + (size_t)(kt + row) * N + n0 + fb_c * 8);
        }
    };

    const int NIT = K / BK;   // 112
    fill(0, 0);  cp_commit();
    fill(1, BK); cp_commit();

    for (int it = 0; it < NIT; it++) {
        cp_wait<1>();
        __syncthreads();

        int nt = it + 2;
        if (nt < NIT) fill(nt % STAGES, nt * BK);
        cp_commit();

        uint32_t sa = smem0 + (it % STAGES) * STG2_B;
        uint32_t sb = sa + TILE_A;

#pragma unroll
        for (int kk = 0; kk < 4; kk++) {
            uint32_t a[2][4], b[4][4];
#pragma unroll
            for (int mt = 0; mt < 2; mt++) {
                int row = a_row + mt * 16;
                int ch  = 2 * kk + a_cb;
                ldm4(a[mt][0], a[mt][1], a[mt][2], a[mt][3],
                     sa + row * 128 + ((ch ^ lr7) << 4));
            }
#pragma unroll
            for (int ntl = 0; ntl < 4; ntl++) {   // n16 tiles within warp's 64 n
                int kr = kk * 16 + bk_l;
                int cn = wn * 8 + ntl * 2 + bn_h;
                ldm4t(b[ntl][0], b[ntl][1], b[ntl][2], b[ntl][3],
                      sb + kr * 256 + ((cn ^ ((kr & 7) << 1)) << 4));
            }
#pragma unroll
            for (int mt = 0; mt < 2; mt++)
#pragma unroll
                for (int ntl = 0; ntl < 4; ntl++) {
                    mma_f16(acc[mt][2 * ntl + 0], a[mt], b[ntl][0], b[ntl][1]);
                    mma_f16(acc[mt][2 * ntl + 1], a[mt], b[ntl][2], b[ntl][3]);
                }
        }
    }

    const int erow = m0 + wm * 32 + (l >> 2);
    const int ecol = n0 + wn * 64 + 2 * (l & 3);
#pragma unroll
    for (int mt = 0; mt < 2; mt++)
#pragma unroll
        for (int j = 0; j < 8; j++) {
            float* p0 = C + (size_t)(erow + mt * 16) * N + ecol + j * 8;
            *reinterpret_cast<float2*>(p0)         = make_float2(acc[mt][j][0], acc[mt][j][1]);
            *reinterpret_cast<float2*>(p0 + 8 * N) = make_float2(acc[mt][j][2], acc[mt][j][3]);
        }
}

// ---------------------------------------------------------------------------
// Launch
// ---------------------------------------------------------------------------
extern "C" void kernel_launch(void* const* d_in, const int* in_sizes, int n_in,
                              void* d_out, int out_size) {
    const float* x  = (const float*)d_in[0];   // (E, M, H)
    const float* w1 = (const float*)d_in[1];   // (E, H, F)
    const float* w2 = (const float*)d_in[2];   // (E, F, H)
    const float* w3 = (const float*)d_in[3];   // (E, H, F)
    float* out = (float*)d_out;                // (E, M, H)

    cudaFuncSetAttribute(gemm1_swiglu,
                         cudaFuncAttributeMaxDynamicSharedMemorySize, SMEM1);
    cudaFuncSetAttribute(gemm_f16,
                         cudaFuncAttributeMaxDynamicSharedMemorySize, SMEM2);

    void *pxc, *pw1, *pw2, *pw3, *ph;
    cudaGetSymbolAddress(&pxc, g_xc);
    cudaGetSymbolAddress(&pw1, g_w1c);
    cudaGetSymbolAddress(&pw2, g_w2c);
    cudaGetSymbolAddress(&pw3, g_w3c);
    cudaGetSymbolAddress(&ph,  g_hid);

    const int nx4 = NE * NM * NH / 4;
    const int nw4 = NE * NH * NF / 4;
    conv_h<<<(nx4 + 255) / 256, 256>>>((const float4*)x,  (__half2*)pxc, nx4);
    conv_h<<<(nw4 + 255) / 256, 256>>>((const float4*)w1, (__half2*)pw1, nw4);
    conv_h<<<(nw4 + 255) / 256, 256>>>((const float4*)w3, (__half2*)pw3, nw4);
    conv_h<<<(nw4 + 255) / 256, 256>>>((const float4*)w2, (__half2*)pw2, nw4);

    // fused: hid = fp16( silu(x*w1) * (x*w3) )
    dim3 g1(NM / BM, NF / BN1, NE);   // 16 x 112 x 8
    gemm1_swiglu<<<g1, NT, SMEM1>>>((const __half*)pxc, (const __half*)pw1,
                                    (const __half*)pw3, (__half*)ph);

    // out = hid * w2
    dim3 g2(NM / BM, NH / BN2, NE);   // 16 x 16 x 8
    gemm_f16<<<g2, NT, SMEM2>>>((const __half*)ph, (const __half*)pw2,
                                out, NH, NF);
}

// round 15
// speedup vs baseline: 1.0018x; 1.0018x over previous
#include <cuda_runtime.h>
#include <cuda_fp16.h>
#include <cstdint>

namespace {
constexpr int NE = 8, NM = 2048, NH = 2048, NF = 7168;

constexpr int BM = 128, BK = 64;           // A rows: 64 fp16 = 128B
constexpr int STAGES = 3;
constexpr int NT = 256;                    // 8 warps

// gemm2 (single-B): BN=128, warp tile 32x64; B tile [BK k-rows][128 n] = 256B/row
constexpr int BN2 = 128;
constexpr int TILE_A  = BM * BK * 2;           // 16384 B
constexpr int TILE_B2 = BK * BN2 * 2;          // 16384 B
constexpr int STG2_B  = TILE_A + TILE_B2;      // 32 KB
constexpr unsigned SMEM2 = STAGES * STG2_B;    // 96 KB

// fused dual gemm1 (B1+B3): BN=64; B tile [BK k-rows][64 n] = 128B/row
constexpr int BN1 = 64;
constexpr int TILE_B1 = BK * BN1 * 2;          // 8192 B
constexpr int STG1_B  = TILE_A + 2 * TILE_B1;  // 32 KB
constexpr unsigned SMEM1 = STAGES * STG1_B;    // 96 KB
}

// ---------------------------------------------------------------------------
// Static device scratch (no cudaMalloc allowed) — all plain fp16 copies,
// SAME layout as the fp32 originals (no transpose needed anymore).
// ---------------------------------------------------------------------------
__device__ __half g_xc [(size_t)NE * NM * NH];   // x   [M, K=H]
__device__ __half g_w1c[(size_t)NE * NH * NF];   // w1  [K=H, N=F]
__device__ __half g_w3c[(size_t)NE * NH * NF];   // w3  [K=H, N=F]
__device__ __half g_w2c[(size_t)NE * NF * NH];   // w2  [K=F, N=H]
__device__ __half g_hid[(size_t)NE * NM * NF];   // hidden [M, K=F]

// ---------------------------------------------------------------------------
// helpers
// ---------------------------------------------------------------------------
__device__ __forceinline__ void cp16(uint32_t dst, const void* src) {
    asm volatile("cp.async.cg.shared.global [%0], [%1], 16;\n" :: "r"(dst), "l"(src));
}
__device__ __forceinline__ void cp_commit() {
    asm volatile("cp.async.commit_group;\n");
}
template <int N> __device__ __forceinline__ void cp_wait() {
    asm volatile("cp.async.wait_group %0;\n" :: "n"(N));
}
__device__ __forceinline__ void ldm4(uint32_t& r0, uint32_t& r1,
                                     uint32_t& r2, uint32_t& r3, uint32_t addr) {
    asm volatile("ldmatrix.sync.aligned.m8n8.x4.shared.b16 {%0,%1,%2,%3}, [%4];"
                 : "=r"(r0), "=r"(r1), "=r"(r2), "=r"(r3) : "r"(addr));
}
__device__ __forceinline__ void ldm4t(uint32_t& r0, uint32_t& r1,
                                      uint32_t& r2, uint32_t& r3, uint32_t addr) {
    asm volatile("ldmatrix.sync.aligned.m8n8.x4.trans.shared.b16 {%0,%1,%2,%3}, [%4];"
                 : "=r"(r0), "=r"(r1), "=r"(r2), "=r"(r3) : "r"(addr));
}
__device__ __forceinline__ void mma_f16(float* c, const uint32_t* a,
                                        uint32_t b0, uint32_t b1) {
    asm volatile(
        "mma.sync.aligned.m16n8k16.row.col.f32.f16.f16.f32 "
        "{%0,%1,%2,%3}, {%4,%5,%6,%7}, {%8,%9}, {%0,%1,%2,%3};"
        : "+f"(c[0]), "+f"(c[1]), "+f"(c[2]), "+f"(c[3])
        : "r"(a[0]), "r"(a[1]), "r"(a[2]), "r"(a[3]), "r"(b0), "r"(b1));
}

// ---------------------------------------------------------------------------
// Elementwise fp32 -> fp16 (fully coalesced, no smem)
// ---------------------------------------------------------------------------
__global__ void conv_h(const float4* __restrict__ in, __half2* __restrict__ out,
                       int n4) {
    int i = blockIdx.x * blockDim.x + threadIdx.x;
    if (i >= n4) return;
    float4 v = in[i];
    out[2 * i + 0] = __floats2half2_rn(v.x, v.y);
    out[2 * i + 1] = __floats2half2_rn(v.z, v.w);
}

// ---------------------------------------------------------------------------
// Fused dual GEMM1 + SwiGLU: hid = fp16( silu(x*w1) * (x*w3) )
//   A [M,K] row-major; B1,B3 [K,N] row-major (weights as-is).
//   grid (NM/BM, NF/BN1, NE); 8 warps 4(m)x2(n); warp tile 32x32 per output.
// A smem: row m (128B), chunk c(0..7)=k8: off = m*128 + ((c^(m&7))<<4)
// B smem: row k (128B, 64 n),  chunk c(0..7)=n8: off = k*128 + ((c^(k&7))<<4)
// ---------------------------------------------------------------------------
__global__ void __launch_bounds__(NT, 2)
gemm1_swiglu(const __half* __restrict__ Ag, const __half* __restrict__ B1g,
             const __half* __restrict__ B3g, __half* __restrict__ Hg) {
    extern __shared__ char smc[];
    const int e  = blockIdx.z;
    const int m0 = blockIdx.x * BM;
    const int n0 = blockIdx.y * BN1;

    const __half* A  = Ag  + (size_t)e * NM * NH;
    const __half* B1 = B1g + (size_t)e * (size_t)NH * NF;
    const __half* B3 = B3g + (size_t)e * (size_t)NH * NF;
    __half*       H  = Hg  + (size_t)e * (size_t)NM * NF;

    const int tid  = threadIdx.x;
    const int warp = tid >> 5;
    const int l    = tid & 31;
    const int wm   = warp >> 1;      // m rows wm*32
    const int wn   = warp & 1;       // n cols wn*32
    const int lr7  = l & 7;

    const uint32_t smem0 = (uint32_t)__cvta_generic_to_shared(smc);

    // A ldmatrix (row-major, non-trans): lanes 0-7 rows lo-16B etc.
    const int a_row = wm * 32 + ((l >> 3) & 1) * 8 + lr7;  // + mt*16
    const int a_cb  = (l >> 4) & 1;                        // k8 sub-chunk
    // B ldmatrix.trans (K-major): lanes 0-7 k0-7/n0, 8-15 k8-15/n0,
    //                             16-23 k0-7/n8, 24-31 k8-15/n8
    const int bk_l  = ((l >> 3) & 1) * 8 + lr7;            // k-lane within k16
    const int bn_h  = (l >> 4) & 1;                        // n8 sub-chunk

    // fills
    const int f_row = tid >> 3;      // +32 rows/step
    const int f_c   = tid & 7;

    float ac1[2][4][4], ac3[2][4][4];
#pragma unroll
    for (int i = 0; i < 2; i++)
#pragma unroll
        for (int j = 0; j < 4; j++)
#pragma unroll
            for (int t = 0; t < 4; t++) { ac1[i][j][t] = 0.f; ac3[i][j][t] = 0.f; }

    auto fill = [&](int st, int kt) {
        uint32_t sa  = smem0 + st * STG1_B;
        uint32_t sb1 = sa + TILE_A;
        uint32_t sb3 = sb1 + TILE_B1;
#pragma unroll
        for (int i = 0; i < 4; i++) {     // A: 128 rows x 8 chunks
            int row = f_row + i * 32;
            uint32_t off = row * 128 + ((f_c ^ (row & 7)) << 4);
            cp16(sa + off, A + (size_t)(m0 + row) * NH + kt + f_c * 8);
        }
#pragma unroll
        for (int i = 0; i < 2; i++) {     // B: 64 k-rows x 8 chunks, two tiles
            int row = f_row + i * 32;
            if (row < BK) {
                uint32_t off = row * 128 + ((f_c ^ (row & 7)) << 4);
                size_t g = (size_t)(kt + row) * NF + n0 + f_c * 8;
                cp16(sb1 + off, B1 + g);
                cp16(sb3 + off, B3 + g);
            }
        }
    };

    const int NIT = NH / BK;   // 32
    fill(0, 0);  cp_commit();
    fill(1, BK); cp_commit();

    for (int it = 0; it < NIT; it++) {
        cp_wait<1>();
        __syncthreads();

        int nt = it + 2;
        if (nt < NIT) fill(nt % STAGES, nt * BK);
        cp_commit();

        uint32_t sa  = smem0 + (it % STAGES) * STG1_B;
        uint32_t sb1 = sa + TILE_A;
        uint32_t sb3 = sb1 + TILE_B1;

#pragma unroll
        for (int kk = 0; kk < 4; kk++) {        // k16 steps
            uint32_t a[2][4], b1[2][4], b3[2][4];
#pragma unroll
            for (int mt = 0; mt < 2; mt++) {
                int row = a_row + mt * 16;
                int ch  = 2 * kk + a_cb;
                ldm4(a[mt][0], a[mt][1], a[mt][2], a[mt][3],
                     sa + row * 128 + ((ch ^ lr7) << 4));
            }
#pragma unroll
            for (int ntl = 0; ntl < 2; ntl++) {   // n16 tiles within warp's 32 n
                int kr = kk * 16 + bk_l;
                int cn = wn * 4 + ntl * 2 + bn_h;
                uint32_t so = kr * 128 + ((cn ^ (kr & 7)) << 4);
                ldm4t(b1[ntl][0], b1[ntl][1], b1[ntl][2], b1[ntl][3], sb1 + so);
                ldm4t(b3[ntl][0], b3[ntl][1], b3[ntl][2], b3[ntl][3], sb3 + so);
            }
#pragma unroll
            for (int mt = 0; mt < 2; mt++)
#pragma unroll
                for (int ntl = 0; ntl < 2; ntl++) {
                    mma_f16(ac1[mt][2 * ntl + 0], a[mt], b1[ntl][0], b1[ntl][1]);
                    mma_f16(ac1[mt][2 * ntl + 1], a[mt], b1[ntl][2], b1[ntl][3]);
                    mma_f16(ac3[mt][2 * ntl + 0], a[mt], b3[ntl][0], b3[ntl][1]);
                    mma_f16(ac3[mt][2 * ntl + 1], a[mt], b3[ntl][2], b3[ntl][3]);
                }
        }
    }

    // SwiGLU epilogue (identical fragment mappings), store fp16 hidden.
    const int erow = m0 + wm * 32 + (l >> 2);
    const int ecol = n0 + wn * 32 + 2 * (l & 3);
#pragma unroll
    for (int mt = 0; mt < 2; mt++)
#pragma unroll
        for (int j = 0; j < 4; j++) {
            float v0 = ac1[mt][j][0], v1 = ac1[mt][j][1];
            float v2 = ac1[mt][j][2], v3 = ac1[mt][j][3];
            float h0 = v0 / (1.0f + __expf(-v0)) * ac3[mt][j][0];
            float h1 = v1 / (1.0f + __expf(-v1)) * ac3[mt][j][1];
            float h2 = v2 / (1.0f + __expf(-v2)) * ac3[mt][j][2];
            float h3 = v3 / (1.0f + __expf(-v3)) * ac3[mt][j][3];
            __half* p0 = H + (size_t)(erow + mt * 16) * NF + ecol + j * 8;
            *reinterpret_cast<__half2*>(p0)          = __floats2half2_rn(h0, h1);
            *reinterpret_cast<__half2*>(p0 + 8 * NF) = __floats2half2_rn(h2, h3);
        }
}

// ---------------------------------------------------------------------------
// GEMM2: out = hid * w2   A [M,K=F] fp16, B=w2 [K=F,N=H] fp16, C fp32.
//   grid (NM/BM, NH/BN2, NE); warp tile 32x64.
// B smem: row k (256B, 128 n), chunk c(0..15)=n8:
//   off = k*256 + ((c ^ ((k&7)<<1)) << 4)
// ---------------------------------------------------------------------------
__global__ void __launch_bounds__(NT, 2)
gemm_f16(const __half* __restrict__ Ag, const __half* __restrict__ Bg,
         float* __restrict__ Cg, int N, int K) {
    extern __shared__ char smc[];
    const int e  = blockIdx.z;
    const int m0 = blockIdx.x * BM;
    const int n0 = blockIdx.y * BN2;

    const __half* A = Ag + (size_t)e * NM * K;
    const __half* B = Bg + (size_t)e * (size_t)K * N;
    float*        C = Cg + (size_t)e * NM * N;

    const int tid  = threadIdx.x;
    const int warp = tid >> 5;
    const int l    = tid & 31;
    const int wm   = warp >> 1;
    const int wn   = warp & 1;       // cols wn*64
    const int lr7  = l & 7;

    const uint32_t smem0 = (uint32_t)__cvta_generic_to_shared(smc);

    const int a_row = wm * 32 + ((l >> 3) & 1) * 8 + lr7;
    const int a_cb  = (l >> 4) & 1;
    const int bk_l  = ((l >> 3) & 1) * 8 + lr7;
    const int bn_h  = (l >> 4) & 1;

    const int fa_row = tid >> 3,  fa_c = tid & 7;     // A fill
    const int fb_row = tid >> 4,  fb_c = tid & 15;    // B fill (16 chunks/row)

    float acc[2][8][4];
#pragma unroll
    for (int i = 0; i < 2; i++)
#pragma unroll
        for (int j = 0; j < 8; j++)
#pragma unroll
            for (int t = 0; t < 4; t++) acc[i][j][t] = 0.0f;

    auto fill = [&](int st, int kt) {
        uint32_t sa = smem0 + st * STG2_B;
        uint32_t sb = sa + TILE_A;
#pragma unroll
        for (int i = 0; i < 4; i++) {     // A: 128 rows x 8 chunks
            int row = fa_row + i * 32;
            uint32_t off = row * 128 + ((fa_c ^ (row & 7)) << 4);
            cp16(sa + off, A + (size_t)(m0 + row) * K + kt + fa_c * 8);
        }
#pragma unroll
        for (int i = 0; i < 4; i++) {     // B: 64 k-rows x 16 chunks
            int row = fb_row + i * 16;
            uint32_t off = row * 256 + ((fb_c ^ ((row & 7) << 1)) << 4);
            cp16(sb + off, B + (size_t)(kt + row) * N + n0 + fb_c * 8);
        }
    };

    const int NIT = K / BK;   // 112
    fill(0, 0);  cp_commit();
    fill(1, BK); cp_commit();

    for (int it = 0; it < NIT; it++) {
        cp_wait<1>();
        __syncthreads();

        int nt = it + 2;
        if (nt < NIT) fill(nt % STAGES, nt * BK);
        cp_commit();

        uint32_t sa = smem0 + (it % STAGES) * STG2_B;
        uint32_t sb = sa + TILE_A;

#pragma unroll
        for (int kk = 0; kk < 4; kk++) {
            uint32_t a[2][4], b[4][4];
#pragma unroll
            for (int mt = 0; mt < 2; mt++) {
                int row = a_row + mt * 16;
                int ch  = 2 * kk + a_cb;
                ldm4(a[mt][0], a[mt][1], a[mt][2], a[mt][3],
                     sa + row * 128 + ((ch ^ lr7) << 4));
            }
#pragma unroll
            for (int ntl = 0; ntl < 4; ntl++) {   // n16 tiles within warp's 64 n
                int kr = kk * 16 + bk_l;
                int cn = wn * 8 + ntl * 2 + bn_h;
                ldm4t(b[ntl][0], b[ntl][1], b[ntl][2], b[ntl][3],
                      sb + kr * 256 + ((cn ^ ((kr & 7) << 1)) << 4));
            }
#pragma unroll
            for (int mt = 0; mt < 2; mt++)
#pragma unroll
                for (int ntl = 0; ntl < 4; ntl++) {
                    mma_f16(acc[mt][2 * ntl + 0], a[mt], b[ntl][0], b[ntl][1]);
                    mma_f16(acc[mt][2 * ntl + 1], a[mt], b[ntl][2], b[ntl][3]);
                }
        }
    }

    const int erow = m0 + wm * 32 + (l >> 2);
    const int ecol = n0 + wn * 64 + 2 * (l & 3);
#pragma unroll
    for (int mt = 0; mt < 2; mt++)
#pragma unroll
        for (int j = 0; j < 8; j++) {
            float* p0 = C + (size_t)(erow + mt * 16) * N + ecol + j * 8;
            *reinterpret_cast<float2*>(p0)         = make_float2(acc[mt][j][0], acc[mt][j][1]);
            *reinterpret_cast<float2*>(p0 + 8 * N) = make_float2(acc[mt][j][2], acc[mt][j][3]);
        }
}

// ---------------------------------------------------------------------------
// Launch
// ---------------------------------------------------------------------------
extern "C" void kernel_launch(void* const* d_in, const int* in_sizes, int n_in,
                              void* d_out, int out_size) {
    const float* x  = (const float*)d_in[0];   // (E, M, H)
    const float* w1 = (const float*)d_in[1];   // (E, H, F)
    const float* w2 = (const float*)d_in[2];   // (E, F, H)
    const float* w3 = (const float*)d_in[3];   // (E, H, F)
    float* out = (float*)d_out;                // (E, M, H)

    cudaFuncSetAttribute(gemm1_swiglu,
                         cudaFuncAttributeMaxDynamicSharedMemorySize, SMEM1);
    cudaFuncSetAttribute(gemm_f16,
                         cudaFuncAttributeMaxDynamicSharedMemorySize, SMEM2);

    void *pxc, *pw1, *pw2, *pw3, *ph;
    cudaGetSymbolAddress(&pxc, g_xc);
    cudaGetSymbolAddress(&pw1, g_w1c);
    cudaGetSymbolAddress(&pw2, g_w2c);
    cudaGetSymbolAddress(&pw3, g_w3c);
    cudaGetSymbolAddress(&ph,  g_hid);

    const int nx4 = NE * NM * NH / 4;
    const int nw4 = NE * NH * NF / 4;
    conv_h<<<(nx4 + 255) / 256, 256>>>((const float4*)x,  (__half2*)pxc, nx4);
    conv_h<<<(nw4 + 255) / 256, 256>>>((const float4*)w1, (__half2*)pw1, nw4);
    conv_h<<<(nw4 + 255) / 256, 256>>>((const float4*)w3, (__half2*)pw3, nw4);
    conv_h<<<(nw4 + 255) / 256, 256>>>((const float4*)w2, (__half2*)pw2, nw4);

    // fused: hid = fp16( silu(x*w1) * (x*w3) )
    dim3 g1(NM / BM, NF / BN1, NE);   // 16 x 112 x 8
    gemm1_swiglu<<<g1, NT, SMEM1>>>((const __half*)pxc, (const __half*)pw1,
                                    (const __half*)pw3, (__half*)ph);

    // out = hid * w2
    dim3 g2(NM / BM, NH / BN2, NE);   // 16 x 16 x 8
    gemm_f16<<<g2, NT, SMEM2>>>((const __half*)ph, (const __half*)pw2,
                                out, NH, NF);
}